// round 12
// baseline (speedup 1.0000x reference)
#include <cuda_runtime.h>
#include <cuda_bf16.h>
#include <math.h>
#include <stdint.h>

// Problem constants
#define NTOK   2048
#define HID    2048
#define INTER_ 1024
#define NEXP   8
#define TOPK   2
#define NSLOT  (NTOK * TOPK)

// ---- gu kernel: 512 thr, C=128x256, 4-stage ----
#define KT      32
#define PLANE_A 8192
#define PLANE_B 16384
#define STAGE   (2 * PLANE_A + 2 * PLANE_B)
#define SM_BUF  1024
#define SLOT(s)   (SM_BUF + (s) * STAGE)
#define OFF_AH  0
#define OFF_AL  PLANE_A
#define OFF_BH  (2 * PLANE_A)
#define OFF_BL  (2 * PLANE_A + PLANE_B)
#define GU_SMEM (SM_BUF + 4 * STAGE)         // 197632
#define CS_STRIDE 264

// ---- down kernel: 256 thr, C=128x128, 3-stage, 2 CTA/SM ----
#define DPLANE  8192
#define DSTAGE  (4 * DPLANE)
#define DSLOT(s) (SM_BUF + (s) * DSTAGE)
#define DN_SMEM (SM_BUF + 3 * DSTAGE)        // 99328

// -------- device scratch --------
__device__ int   g_counts[NEXP];
__device__ int   g_offsets[NEXP];
__device__ int   g_token[NSLOT];
__device__ int   g_pos[NSLOT];
__device__ float g_weight[NSLOT];
__device__ float g_dout[(size_t)NSLOT * HID];
__device__ __nv_bfloat16 g_xh[(size_t)NTOK * HID];
__device__ __nv_bfloat16 g_xl[(size_t)NTOK * HID];
__device__ __nv_bfloat16 g_gh[(size_t)NEXP * INTER_ * HID];
__device__ __nv_bfloat16 g_gl[(size_t)NEXP * INTER_ * HID];
__device__ __nv_bfloat16 g_uh[(size_t)NEXP * INTER_ * HID];
__device__ __nv_bfloat16 g_ul[(size_t)NEXP * INTER_ * HID];
__device__ __nv_bfloat16 g_dh[(size_t)NEXP * HID * INTER_];
__device__ __nv_bfloat16 g_dl[(size_t)NEXP * HID * INTER_];
__device__ __nv_bfloat16 g_ih[(size_t)NSLOT * INTER_];
__device__ __nv_bfloat16 g_il[(size_t)NSLOT * INTER_];

// ---------------- helpers ----------------
__device__ __forceinline__ uint32_t smem_u32(const void* p) {
    uint32_t a;
    asm("{ .reg .u64 t; cvta.to.shared.u64 t, %1; cvt.u32.u64 %0, t; }" : "=r"(a) : "l"(p));
    return a;
}
#define CP16(sm, gm) asm volatile("cp.async.cg.shared.global [%0], [%1], 16;" :: "r"(sm), "l"(gm))
#define CP_COMMIT()  asm volatile("cp.async.commit_group;" ::: "memory")
#define CP_WAIT(n)   asm volatile("cp.async.wait_group %0;" :: "n"(n) : "memory")

__device__ __forceinline__ void mma_bf16(float* c, const uint32_t* a, const uint32_t* b) {
    asm volatile(
        "mma.sync.aligned.m16n8k16.row.col.f32.bf16.bf16.f32 "
        "{%0,%1,%2,%3}, {%4,%5,%6,%7}, {%8,%9}, {%0,%1,%2,%3};\n"
        : "+f"(c[0]), "+f"(c[1]), "+f"(c[2]), "+f"(c[3])
        : "r"(a[0]), "r"(a[1]), "r"(a[2]), "r"(a[3]), "r"(b[0]), "r"(b[1]));
}
__device__ __forceinline__ void ldm_x4(uint32_t* r, uint32_t addr) {
    asm volatile("ldmatrix.sync.aligned.m8n8.x4.shared.b16 {%0,%1,%2,%3}, [%4];"
        : "=r"(r[0]), "=r"(r[1]), "=r"(r[2]), "=r"(r[3]) : "r"(addr));
}
__device__ __forceinline__ uint32_t swz(int row, int chunk) {
    return (uint32_t)((row << 6) + (((chunk ^ ((row >> 1) & 3))) << 4));
}
__device__ __forceinline__ uint32_t packhl(float a, float b, float& ra, float& rb) {
    __nv_bfloat16 ha = __float2bfloat16(a);
    __nv_bfloat16 hb = __float2bfloat16(b);
    ra = a - __bfloat162float(ha);
    rb = b - __bfloat162float(hb);
    __nv_bfloat162 p = __halves2bfloat162(ha, hb);
    return *reinterpret_cast<uint32_t*>(&p);
}
__device__ __forceinline__ uint32_t packlo(float a, float b) {
    __nv_bfloat162 p = __halves2bfloat162(__float2bfloat16(a), __float2bfloat16(b));
    return *reinterpret_cast<uint32_t*>(&p);
}

// ---------------- splits ----------------
__global__ void split_xgu(const float4* __restrict__ xs,
                          const float4* __restrict__ gs,
                          const float4* __restrict__ us,
                          uint2* __restrict__ xh, uint2* __restrict__ xl,
                          uint2* __restrict__ gh, uint2* __restrict__ gl,
                          uint2* __restrict__ uh, uint2* __restrict__ ul) {
    const int nw = NEXP * INTER_ * HID / 4;
    const int nx = NTOK * HID / 4;
    int i = blockIdx.x * blockDim.x + threadIdx.x;
    const float4* src; uint2 *H, *L; int j;
    if (i < nw)               { src = gs; H = gh; L = gl; j = i; }
    else if (i < 2 * nw)      { src = us; H = uh; L = ul; j = i - nw; }
    else if (i < 2 * nw + nx) { src = xs; H = xh; L = xl; j = i - 2 * nw; }
    else return;
    float4 v = src[j];
    float rx, ry, rz, rw;
    uint2 Hv, Lv;
    Hv.x = packhl(v.x, v.y, rx, ry);
    Hv.y = packhl(v.z, v.w, rz, rw);
    Lv.x = packlo(rx, ry);
    Lv.y = packlo(rz, rw);
    H[j] = Hv;
    L[j] = Lv;
}
__global__ void split_down_k(const float4* __restrict__ ds,
                             uint2* __restrict__ dh, uint2* __restrict__ dl, int n4) {
    int i = blockIdx.x * blockDim.x + threadIdx.x;
    if (i >= n4) return;
    float4 v = ds[i];
    float rx, ry, rz, rw;
    uint2 Hv, Lv;
    Hv.x = packhl(v.x, v.y, rx, ry);
    Hv.y = packhl(v.z, v.w, rz, rw);
    Lv.x = packlo(rx, ry);
    Lv.y = packlo(rz, rw);
    dh[i] = Hv;
    dl[i] = Lv;
}

// ---------------- routing ----------------
__global__ void route_kernel(const int* __restrict__ idxw,
                             const float* __restrict__ wts) {
    __shared__ int cnt[NEXP], off[NEXP], cur[NEXP];
    __shared__ int not64;
    int tid = threadIdx.x;
    if (tid < NEXP) { cnt[tid] = 0; cur[tid] = 0; }
    if (tid == 0) not64 = 0;
    __syncthreads();
    int any = 0;
    for (int i = 2 * tid + 1; i < NSLOT; i += 2 * blockDim.x) any |= idxw[i];
    if (any) atomicOr(&not64, 1);
    __syncthreads();
    const int is64 = !not64;
    for (int s = tid; s < NSLOT; s += blockDim.x) {
        int e = is64 ? idxw[2 * s] : idxw[s];
        atomicAdd(&cnt[e], 1);
    }
    __syncthreads();
    if (tid == 0) {
        int acc = 0;
        for (int e = 0; e < NEXP; e++) {
            off[e] = acc; g_offsets[e] = acc; g_counts[e] = cnt[e];
            acc += cnt[e];
        }
    }
    __syncthreads();
    for (int s = tid; s < NSLOT; s += blockDim.x) {
        int e = is64 ? idxw[2 * s] : idxw[s];
        int p = off[e] + atomicAdd(&cur[e], 1);
        g_token[p]  = s >> 1;
        g_weight[p] = wts[s];
        g_pos[s]    = p;
    }
}

// ---------------- gather ----------------
__global__ void gather_kernel(float4* __restrict__ out) {
    int i = blockIdx.x * blockDim.x + threadIdx.x;
    if (i >= NTOK * HID / 4) return;
    int t = i / (HID / 4);
    int h = i - t * (HID / 4);
    const float4* r0 = (const float4*)(g_dout + (size_t)g_pos[2 * t] * HID) + h;
    const float4* r1 = (const float4*)(g_dout + (size_t)g_pos[2 * t + 1] * HID) + h;
    float4 a = *r0, b = *r1;
    out[i] = make_float4(a.x + b.x, a.y + b.y, a.z + b.z, a.w + b.w);
}

// ---------------- GEMM 1: gate+up, C=128x(128g|128u), 4-stage, 512thr ----
__global__ __launch_bounds__(512, 1)
void gemm_gu_mma(void) {
    const int e   = blockIdx.z;
    const int cnt = g_counts[e];
    const int m0  = blockIdx.y * 128;
    if (m0 >= cnt) return;
    const int base = g_offsets[e];
    const int n0   = blockIdx.x * 128;

    extern __shared__ char smem[];
    const uint32_t sb = smem_u32(smem);
    int*   sTok = (int*)smem;
    float* sW   = (float*)(smem + 512);

    const int tid  = threadIdx.x;
    const int wid  = tid >> 5;
    const int lane = tid & 31;

    if (tid < 128) {
        int m = m0 + tid;
        int r = base + (m < cnt ? m : cnt - 1);
        sTok[tid] = g_token[r];
        sW[tid]   = (m < cnt) ? g_weight[r] : 0.f;
    }
    __syncthreads();

    const int lrow  = tid >> 1;
    const int lhalf = tid & 1;
    const int ge0 = lhalf * 16, ge1 = lhalf * 16 + 8;
    const __nv_bfloat16* aRowH = g_xh + (size_t)sTok[lrow & 127] * HID;
    const __nv_bfloat16* aRowL = g_xl + (size_t)sTok[lrow & 127] * HID;
    const uint32_t soA0 = swz(lrow & 127, lhalf * 2);
    const uint32_t soA1 = swz(lrow & 127, lhalf * 2 + 1);
    const __nv_bfloat16* bRowH = (lrow < 128)
        ? g_gh + ((size_t)e * INTER_ + n0 + lrow) * HID
        : g_uh + ((size_t)e * INTER_ + n0 + lrow - 128) * HID;
    const __nv_bfloat16* bRowL = (lrow < 128)
        ? g_gl + ((size_t)e * INTER_ + n0 + lrow) * HID
        : g_ul + ((size_t)e * INTER_ + n0 + lrow - 128) * HID;
    const uint32_t soB0 = swz(lrow, lhalf * 2);
    const uint32_t soB1 = swz(lrow, lhalf * 2 + 1);
    const bool doA = (tid < 256);

    const int wm = wid >> 3, wn = wid & 7;
    const int g  = lane >> 2, t4 = lane & 3;
    const int lg = lane >> 3, lr7 = lane & 7;

    int rowA[4], xA[4];
    #pragma unroll
    for (int mt = 0; mt < 4; mt++) {
        rowA[mt] = wm * 64 + mt * 16 + (lg & 1) * 8 + lr7;
        xA[mt]   = (rowA[mt] >> 1) & 3;
    }
    int rowB[2], xB[2];
    #pragma unroll
    for (int p = 0; p < 2; p++) {
        rowB[p] = wn * 32 + (2 * p + (lg >> 1)) * 8 + lr7;
        xB[p]   = (rowB[p] >> 1) & 3;
    }

    float acc[4][4][4];
    #pragma unroll
    for (int i = 0; i < 4; i++)
        #pragma unroll
        for (int j = 0; j < 4; j++)
            #pragma unroll
            for (int r = 0; r < 4; r++) acc[i][j][r] = 0.f;

    const int NT = HID / KT;   // 64

    #pragma unroll
    for (int s = 0; s < 3; s++) {
        uint32_t d = sb + SLOT(s);
        int k0 = s * KT;
        if (doA) {
            CP16(d + OFF_AH + soA0, aRowH + k0 + ge0);
            CP16(d + OFF_AH + soA1, aRowH + k0 + ge1);
            CP16(d + OFF_AL + soA0, aRowL + k0 + ge0);
            CP16(d + OFF_AL + soA1, aRowL + k0 + ge1);
        }
        CP16(d + OFF_BH + soB0, bRowH + k0 + ge0);
        CP16(d + OFF_BH + soB1, bRowH + k0 + ge1);
        CP16(d + OFF_BL + soB0, bRowL + k0 + ge0);
        CP16(d + OFF_BL + soB1, bRowL + k0 + ge1);
        CP_COMMIT();
    }

    int slot = 0, wslot = 3;
    for (int t = 0; t < NT; t++) {
        if (t + 2 < NT)      { CP_WAIT(2); }
        else if (t + 1 < NT) { CP_WAIT(1); }
        else                 { CP_WAIT(0); }
        __syncthreads();
        if (t + 3 < NT) {
            uint32_t d = sb + SLOT(wslot);
            int k0 = (t + 3) * KT;
            if (doA) {
                CP16(d + OFF_AH + soA0, aRowH + k0 + ge0);
                CP16(d + OFF_AH + soA1, aRowH + k0 + ge1);
                CP16(d + OFF_AL + soA0, aRowL + k0 + ge0);
                CP16(d + OFF_AL + soA1, aRowL + k0 + ge1);
            }
            CP16(d + OFF_BH + soB0, bRowH + k0 + ge0);
            CP16(d + OFF_BH + soB1, bRowH + k0 + ge1);
            CP16(d + OFF_BL + soB0, bRowL + k0 + ge0);
            CP16(d + OFF_BL + soB1, bRowL + k0 + ge1);
            CP_COMMIT();
        }
        const uint32_t sa = sb + SLOT(slot);
        #pragma unroll
        for (int ks = 0; ks < 2; ks++) {
            const int cA = ks * 2 + (lg >> 1);
            const int cB = ks * 2 + (lg & 1);
            uint32_t bh[2][4], bl[2][4];
            #pragma unroll
            for (int p = 0; p < 2; p++) {
                uint32_t ab = sa + OFF_BH + (rowB[p] << 6) + (((cB ^ xB[p])) << 4);
                ldm_x4(bh[p], ab);
                ldm_x4(bl[p], ab + PLANE_B);
            }
            #pragma unroll
            for (int mt = 0; mt < 4; mt++) {
                uint32_t aa = sa + OFF_AH + (rowA[mt] << 6) + (((cA ^ xA[mt])) << 4);
                uint32_t ah[4], al[4];
                ldm_x4(ah, aa);
                ldm_x4(al, aa + PLANE_A);
                // term-outer ordering: dependent writes to each accumulator are
                // separated by 4 independent MMAs (breaks the HMMA RAW stall).
                #pragma unroll
                for (int nt = 0; nt < 4; nt++)
                    mma_bf16(acc[mt][nt], al, &bh[nt >> 1][(nt & 1) * 2]);
                #pragma unroll
                for (int nt = 0; nt < 4; nt++)
                    mma_bf16(acc[mt][nt], ah, &bl[nt >> 1][(nt & 1) * 2]);
                #pragma unroll
                for (int nt = 0; nt < 4; nt++)
                    mma_bf16(acc[mt][nt], ah, &bh[nt >> 1][(nt & 1) * 2]);
            }
        }
        slot  = (slot  == 3) ? 0 : slot + 1;
        wslot = (wslot == 3) ? 0 : wslot + 1;
    }
    __syncthreads();

    float* Cs = (float*)(smem + SM_BUF);
    #pragma unroll
    for (int mt = 0; mt < 4; mt++) {
        #pragma unroll
        for (int nt = 0; nt < 4; nt++) {
            int row = wm * 64 + mt * 16 + g;
            int col = wn * 32 + nt * 8 + t4 * 2;
            *reinterpret_cast<float2*>(&Cs[row * CS_STRIDE + col]) =
                make_float2(acc[mt][nt][0], acc[mt][nt][1]);
            *reinterpret_cast<float2*>(&Cs[(row + 8) * CS_STRIDE + col]) =
                make_float2(acc[mt][nt][2], acc[mt][nt][3]);
        }
    }
    __syncthreads();

    const int jj = (tid & 31) * 4;
    const int rb = (tid >> 5) * 8;
    #pragma unroll
    for (int mm = 0; mm < 8; mm++) {
        int m = rb + mm;
        if (m0 + m >= cnt) continue;
        float w = sW[m];
        float4 gv = *reinterpret_cast<const float4*>(&Cs[m * CS_STRIDE + jj]);
        float4 uv = *reinterpret_cast<const float4*>(&Cs[m * CS_STRIDE + 128 + jj]);
        float o0 = (gv.x / (1.f + __expf(-gv.x))) * uv.x * w;
        float o1 = (gv.y / (1.f + __expf(-gv.y))) * uv.y * w;
        float o2 = (gv.z / (1.f + __expf(-gv.z))) * uv.z * w;
        float o3 = (gv.w / (1.f + __expf(-gv.w))) * uv.w * w;
        float r0, r1, r2, r3;
        uint2 H, L;
        H.x = packhl(o0, o1, r0, r1);
        H.y = packhl(o2, o3, r2, r3);
        L.x = packlo(r0, r1);
        L.y = packlo(r2, r3);
        size_t idx = (size_t)(base + m0 + m) * INTER_ + n0 + jj;
        *reinterpret_cast<uint2*>(&g_ih[idx]) = H;
        *reinterpret_cast<uint2*>(&g_il[idx]) = L;
    }
}

// ---------------- GEMM 2: down, 256thr, 128x128, 3-stage ------------------
__global__ __launch_bounds__(256, 2)
void gemm_down_mma(void) {
    const int e   = blockIdx.z;
    const int cnt = g_counts[e];
    const int m0  = blockIdx.y * 128;
    if (m0 >= cnt) return;
    const int base = g_offsets[e];
    const int n0   = blockIdx.x * 128;

    extern __shared__ char smem[];
    const uint32_t sb = smem_u32(smem);

    const int tid  = threadIdx.x;
    const int wid  = tid >> 5;
    const int lane = tid & 31;

    const int lrow  = tid >> 1;
    const int lhalf = tid & 1;
    int ar = base + m0 + lrow; if (ar > NSLOT - 1) ar = NSLOT - 1;
    const __nv_bfloat16* aRowH = g_ih + (size_t)ar * INTER_;
    const __nv_bfloat16* aRowL = g_il + (size_t)ar * INTER_;
    const __nv_bfloat16* bRowH = g_dh + ((size_t)e * HID + n0 + lrow) * INTER_;
    const __nv_bfloat16* bRowL = g_dl + ((size_t)e * HID + n0 + lrow) * INTER_;
    const uint32_t so0 = swz(lrow, lhalf * 2);
    const uint32_t so1 = swz(lrow, lhalf * 2 + 1);
    const int ge0 = lhalf * 16, ge1 = lhalf * 16 + 8;

    const int wm = wid >> 2, wn = wid & 3;
    const int g  = lane >> 2, t4 = lane & 3;
    const int lg = lane >> 3, lr7 = lane & 7;

    int rowA[4], xA[4];
    #pragma unroll
    for (int mt = 0; mt < 4; mt++) {
        rowA[mt] = wm * 64 + mt * 16 + (lg & 1) * 8 + lr7;
        xA[mt]   = (rowA[mt] >> 1) & 3;
    }
    int rowB[2], xB[2];
    #pragma unroll
    for (int p = 0; p < 2; p++) {
        rowB[p] = wn * 32 + (2 * p + (lg >> 1)) * 8 + lr7;
        xB[p]   = (rowB[p] >> 1) & 3;
    }

    float acc[4][4][4];
    #pragma unroll
    for (int i = 0; i < 4; i++)
        #pragma unroll
        for (int j = 0; j < 4; j++)
            #pragma unroll
            for (int r = 0; r < 4; r++) acc[i][j][r] = 0.f;

    const int NT = INTER_ / KT;   // 32

    #pragma unroll
    for (int s = 0; s < 2; s++) {
        uint32_t d = sb + DSLOT(s);
        int k0 = s * KT;
        CP16(d + so0,              aRowH + k0 + ge0);
        CP16(d + so1,              aRowH + k0 + ge1);
        CP16(d + DPLANE + so0,     aRowL + k0 + ge0);
        CP16(d + DPLANE + so1,     aRowL + k0 + ge1);
        CP16(d + 2 * DPLANE + so0, bRowH + k0 + ge0);
        CP16(d + 2 * DPLANE + so1, bRowH + k0 + ge1);
        CP16(d + 3 * DPLANE + so0, bRowL + k0 + ge0);
        CP16(d + 3 * DPLANE + so1, bRowL + k0 + ge1);
        CP_COMMIT();
    }

    int slot = 0, wslot = 2;
    for (int t = 0; t < NT; t++) {
        if (t < NT - 1) { CP_WAIT(1); } else { CP_WAIT(0); }
        __syncthreads();
        if (t + 2 < NT) {
            uint32_t d = sb + DSLOT(wslot);
            int k0 = (t + 2) * KT;
            CP16(d + so0,              aRowH + k0 + ge0);
            CP16(d + so1,              aRowH + k0 + ge1);
            CP16(d + DPLANE + so0,     aRowL + k0 + ge0);
            CP16(d + DPLANE + so1,     aRowL + k0 + ge1);
            CP16(d + 2 * DPLANE + so0, bRowH + k0 + ge0);
            CP16(d + 2 * DPLANE + so1, bRowH + k0 + ge1);
            CP16(d + 3 * DPLANE + so0, bRowL + k0 + ge0);
            CP16(d + 3 * DPLANE + so1, bRowL + k0 + ge1);
            CP_COMMIT();
        }
        const uint32_t sa = sb + DSLOT(slot);
        #pragma unroll
        for (int ks = 0; ks < 2; ks++) {
            const int cA = ks * 2 + (lg >> 1);
            const int cB = ks * 2 + (lg & 1);
            uint32_t bh[2][4], bl[2][4];
            #pragma unroll
            for (int p = 0; p < 2; p++) {
                uint32_t ab = sa + 2 * DPLANE + (rowB[p] << 6) + (((cB ^ xB[p])) << 4);
                ldm_x4(bh[p], ab);
                ldm_x4(bl[p], ab + DPLANE);
            }
            #pragma unroll
            for (int mt = 0; mt < 4; mt++) {
                uint32_t aa = sa + (rowA[mt] << 6) + (((cA ^ xA[mt])) << 4);
                uint32_t ah[4], al[4];
                ldm_x4(ah, aa);
                ldm_x4(al, aa + DPLANE);
                #pragma unroll
                for (int nt = 0; nt < 4; nt++)
                    mma_bf16(acc[mt][nt], al, &bh[nt >> 1][(nt & 1) * 2]);
                #pragma unroll
                for (int nt = 0; nt < 4; nt++)
                    mma_bf16(acc[mt][nt], ah, &bl[nt >> 1][(nt & 1) * 2]);
                #pragma unroll
                for (int nt = 0; nt < 4; nt++)
                    mma_bf16(acc[mt][nt], ah, &bh[nt >> 1][(nt & 1) * 2]);
            }
        }
        slot  = (slot  == 2) ? 0 : slot + 1;
        wslot = (wslot == 2) ? 0 : wslot + 1;
    }

    // dense store to g_dout (sorted slot order)
    #pragma unroll
    for (int mt = 0; mt < 4; mt++) {
        int row0 = wm * 64 + mt * 16 + g;
        int row1 = row0 + 8;
        bool v0 = (m0 + row0 < cnt);
        bool v1 = (m0 + row1 < cnt);
        float* o0 = g_dout + (size_t)(base + m0 + row0) * HID + n0;
        float* o1 = g_dout + (size_t)(base + m0 + row1) * HID + n0;
        #pragma unroll
        for (int nt = 0; nt < 4; nt++) {
            int col = wn * 32 + nt * 8 + t4 * 2;
            if (v0) *reinterpret_cast<float2*>(&o0[col]) =
                        make_float2(acc[mt][nt][0], acc[mt][nt][1]);
            if (v1) *reinterpret_cast<float2*>(&o1[col]) =
                        make_float2(acc[mt][nt][2], acc[mt][nt][3]);
        }
    }
}

// ---------------- stream/event handles ----------------
static cudaStream_t g_s2 = nullptr;
static cudaEvent_t  g_evF = nullptr, g_evJ = nullptr;
static struct _StreamInit {
    _StreamInit() {
        if (cudaStreamCreateWithFlags(&g_s2, cudaStreamNonBlocking) != cudaSuccess) g_s2 = nullptr;
        if (cudaEventCreateWithFlags(&g_evF, cudaEventDisableTiming) != cudaSuccess) g_evF = nullptr;
        if (cudaEventCreateWithFlags(&g_evJ, cudaEventDisableTiming) != cudaSuccess) g_evJ = nullptr;
    }
} g_stream_init;

// ---------------- launch ----------------
extern "C" void kernel_launch(void* const* d_in, const int* in_sizes, int n_in,
                              void* d_out, int out_size) {
    const float* x    = (const float*)d_in[0];
    const int*   idxw = (const int*)d_in[1];
    const float* wts  = (const float*)d_in[2];
    const float* gate = (const float*)d_in[3];
    const float* up   = (const float*)d_in[4];
    const float* down = (const float*)d_in[5];
    float* out = (float*)d_out;

    cudaFuncSetAttribute(gemm_gu_mma,   cudaFuncAttributeMaxDynamicSharedMemorySize, GU_SMEM);
    cudaFuncSetAttribute(gemm_down_mma, cudaFuncAttributeMaxDynamicSharedMemorySize, DN_SMEM);

    __nv_bfloat16 *xh, *xl, *gh, *gl, *uh, *ul, *dh, *dl;
    cudaGetSymbolAddress((void**)&xh, g_xh);
    cudaGetSymbolAddress((void**)&xl, g_xl);
    cudaGetSymbolAddress((void**)&gh, g_gh);
    cudaGetSymbolAddress((void**)&gl, g_gl);
    cudaGetSymbolAddress((void**)&uh, g_uh);
    cudaGetSymbolAddress((void**)&ul, g_ul);
    cudaGetSymbolAddress((void**)&dh, g_dh);
    cudaGetSymbolAddress((void**)&dl, g_dl);

    const int nw = NEXP * INTER_ * HID / 4;
    const bool use_streams = (g_s2 && g_evF && g_evJ);

    if (use_streams) {
        cudaEventRecord(g_evF, 0);
        cudaStreamWaitEvent(g_s2, g_evF, 0);
        split_down_k<<<(nw + 255) / 256, 256, 0, g_s2>>>(
            (const float4*)down, (uint2*)dh, (uint2*)dl, nw);
        cudaEventRecord(g_evJ, g_s2);
    } else {
        split_down_k<<<(nw + 255) / 256, 256>>>(
            (const float4*)down, (uint2*)dh, (uint2*)dl, nw);
    }

    route_kernel<<<1, 256>>>(idxw, wts);
    {
        int total = 2 * nw + NTOK * HID / 4;
        split_xgu<<<(total + 255) / 256, 256>>>(
            (const float4*)x, (const float4*)gate, (const float4*)up,
            (uint2*)xh, (uint2*)xl, (uint2*)gh, (uint2*)gl, (uint2*)uh, (uint2*)ul);
    }
    {
        dim3 grid(INTER_ / 128, NSLOT / 128, NEXP);
        gemm_gu_mma<<<grid, 512, GU_SMEM>>>();
    }
    if (use_streams) {
        cudaStreamWaitEvent(0, g_evJ, 0);
    }
    {
        dim3 grid(HID / 128, NSLOT / 128, NEXP);
        gemm_down_mma<<<grid, 256, DN_SMEM>>>();
    }
    {
        int ng = NTOK * HID / 4;
        gather_kernel<<<(ng + 255) / 256, 256>>>((float4*)out);
    }
}

// round 13
// speedup vs baseline: 1.0046x; 1.0046x over previous
#include <cuda_runtime.h>
#include <cuda_bf16.h>
#include <math.h>
#include <stdint.h>

// Problem constants
#define NTOK   2048
#define HID    2048
#define INTER_ 1024
#define NEXP   8
#define TOPK   2
#define NSLOT  (NTOK * TOPK)

// ---- gu kernel: 512 thr, C=128x256, 4-stage ----
#define KT      32
#define PLANE_A 8192
#define PLANE_B 16384
#define STAGE   (2 * PLANE_A + 2 * PLANE_B)
#define SM_BUF  1024
#define SLOT(s)   (SM_BUF + (s) * STAGE)
#define OFF_AH  0
#define OFF_AL  PLANE_A
#define OFF_BH  (2 * PLANE_A)
#define OFF_BL  (2 * PLANE_A + PLANE_B)
#define GU_SMEM (SM_BUF + 4 * STAGE)         // 197632
#define CS_STRIDE 264

// ---- down kernel: 256 thr (8 warps 2x4), C=64x128, warp 32x32, 3-stage, 3 CTA/SM ----
#define DPA 4096                   // A plane: 64 rows * 64B
#define DPB 8192                   // B plane: 128 rows * 64B
#define DSTAGE (2 * DPA + 2 * DPB) // 24576
#define DSLOT(s) (SM_BUF + (s) * DSTAGE)
#define D_AH 0
#define D_AL DPA
#define D_BH (2 * DPA)
#define D_BL (2 * DPA + DPB)
#define DN_SMEM (SM_BUF + 3 * DSTAGE)   // 74752

// -------- device scratch --------
__device__ int   g_counts[NEXP];
__device__ int   g_offsets[NEXP];
__device__ int   g_token[NSLOT];
__device__ int   g_pos[NSLOT];
__device__ float g_weight[NSLOT];
__device__ float g_dout[(size_t)NSLOT * HID];
__device__ __nv_bfloat16 g_xh[(size_t)NTOK * HID];
__device__ __nv_bfloat16 g_xl[(size_t)NTOK * HID];
__device__ __nv_bfloat16 g_gh[(size_t)NEXP * INTER_ * HID];
__device__ __nv_bfloat16 g_gl[(size_t)NEXP * INTER_ * HID];
__device__ __nv_bfloat16 g_uh[(size_t)NEXP * INTER_ * HID];
__device__ __nv_bfloat16 g_ul[(size_t)NEXP * INTER_ * HID];
__device__ __nv_bfloat16 g_dh[(size_t)NEXP * HID * INTER_];
__device__ __nv_bfloat16 g_dl[(size_t)NEXP * HID * INTER_];
__device__ __nv_bfloat16 g_ih[(size_t)NSLOT * INTER_];
__device__ __nv_bfloat16 g_il[(size_t)NSLOT * INTER_];

// ---------------- helpers ----------------
__device__ __forceinline__ uint32_t smem_u32(const void* p) {
    uint32_t a;
    asm("{ .reg .u64 t; cvta.to.shared.u64 t, %1; cvt.u32.u64 %0, t; }" : "=r"(a) : "l"(p));
    return a;
}
#define CP16(sm, gm) asm volatile("cp.async.cg.shared.global [%0], [%1], 16;" :: "r"(sm), "l"(gm))
#define CP_COMMIT()  asm volatile("cp.async.commit_group;" ::: "memory")
#define CP_WAIT(n)   asm volatile("cp.async.wait_group %0;" :: "n"(n) : "memory")

__device__ __forceinline__ void mma_bf16(float* c, const uint32_t* a, const uint32_t* b) {
    asm volatile(
        "mma.sync.aligned.m16n8k16.row.col.f32.bf16.bf16.f32 "
        "{%0,%1,%2,%3}, {%4,%5,%6,%7}, {%8,%9}, {%0,%1,%2,%3};\n"
        : "+f"(c[0]), "+f"(c[1]), "+f"(c[2]), "+f"(c[3])
        : "r"(a[0]), "r"(a[1]), "r"(a[2]), "r"(a[3]), "r"(b[0]), "r"(b[1]));
}
__device__ __forceinline__ void ldm_x4(uint32_t* r, uint32_t addr) {
    asm volatile("ldmatrix.sync.aligned.m8n8.x4.shared.b16 {%0,%1,%2,%3}, [%4];"
        : "=r"(r[0]), "=r"(r[1]), "=r"(r[2]), "=r"(r[3]) : "r"(addr));
}
__device__ __forceinline__ uint32_t swz(int row, int chunk) {
    return (uint32_t)((row << 6) + (((chunk ^ ((row >> 1) & 3))) << 4));
}
__device__ __forceinline__ uint32_t packhl(float a, float b, float& ra, float& rb) {
    __nv_bfloat16 ha = __float2bfloat16(a);
    __nv_bfloat16 hb = __float2bfloat16(b);
    ra = a - __bfloat162float(ha);
    rb = b - __bfloat162float(hb);
    __nv_bfloat162 p = __halves2bfloat162(ha, hb);
    return *reinterpret_cast<uint32_t*>(&p);
}
__device__ __forceinline__ uint32_t packlo(float a, float b) {
    __nv_bfloat162 p = __halves2bfloat162(__float2bfloat16(a), __float2bfloat16(b));
    return *reinterpret_cast<uint32_t*>(&p);
}

// ---------------- splits ----------------
__global__ void split_xgu(const float4* __restrict__ xs,
                          const float4* __restrict__ gs,
                          const float4* __restrict__ us,
                          uint2* __restrict__ xh, uint2* __restrict__ xl,
                          uint2* __restrict__ gh, uint2* __restrict__ gl,
                          uint2* __restrict__ uh, uint2* __restrict__ ul) {
    const int nw = NEXP * INTER_ * HID / 4;
    const int nx = NTOK * HID / 4;
    int i = blockIdx.x * blockDim.x + threadIdx.x;
    const float4* src; uint2 *H, *L; int j;
    if (i < nw)               { src = gs; H = gh; L = gl; j = i; }
    else if (i < 2 * nw)      { src = us; H = uh; L = ul; j = i - nw; }
    else if (i < 2 * nw + nx) { src = xs; H = xh; L = xl; j = i - 2 * nw; }
    else return;
    float4 v = src[j];
    float rx, ry, rz, rw;
    uint2 Hv, Lv;
    Hv.x = packhl(v.x, v.y, rx, ry);
    Hv.y = packhl(v.z, v.w, rz, rw);
    Lv.x = packlo(rx, ry);
    Lv.y = packlo(rz, rw);
    H[j] = Hv;
    L[j] = Lv;
}
__global__ void split_down_k(const float4* __restrict__ ds,
                             uint2* __restrict__ dh, uint2* __restrict__ dl, int n4) {
    int i = blockIdx.x * blockDim.x + threadIdx.x;
    if (i >= n4) return;
    float4 v = ds[i];
    float rx, ry, rz, rw;
    uint2 Hv, Lv;
    Hv.x = packhl(v.x, v.y, rx, ry);
    Hv.y = packhl(v.z, v.w, rz, rw);
    Lv.x = packlo(rx, ry);
    Lv.y = packlo(rz, rw);
    dh[i] = Hv;
    dl[i] = Lv;
}

// ---------------- routing ----------------
__global__ void route_kernel(const int* __restrict__ idxw,
                             const float* __restrict__ wts) {
    __shared__ int cnt[NEXP], off[NEXP], cur[NEXP];
    __shared__ int not64;
    int tid = threadIdx.x;
    if (tid < NEXP) { cnt[tid] = 0; cur[tid] = 0; }
    if (tid == 0) not64 = 0;
    __syncthreads();
    int any = 0;
    for (int i = 2 * tid + 1; i < NSLOT; i += 2 * blockDim.x) any |= idxw[i];
    if (any) atomicOr(&not64, 1);
    __syncthreads();
    const int is64 = !not64;
    for (int s = tid; s < NSLOT; s += blockDim.x) {
        int e = is64 ? idxw[2 * s] : idxw[s];
        atomicAdd(&cnt[e], 1);
    }
    __syncthreads();
    if (tid == 0) {
        int acc = 0;
        for (int e = 0; e < NEXP; e++) {
            off[e] = acc; g_offsets[e] = acc; g_counts[e] = cnt[e];
            acc += cnt[e];
        }
    }
    __syncthreads();
    for (int s = tid; s < NSLOT; s += blockDim.x) {
        int e = is64 ? idxw[2 * s] : idxw[s];
        int p = off[e] + atomicAdd(&cur[e], 1);
        g_token[p]  = s >> 1;
        g_weight[p] = wts[s];
        g_pos[s]    = p;
    }
}

// ---------------- gather ----------------
__global__ void gather_kernel(float4* __restrict__ out) {
    int i = blockIdx.x * blockDim.x + threadIdx.x;
    if (i >= NTOK * HID / 4) return;
    int t = i / (HID / 4);
    int h = i - t * (HID / 4);
    const float4* r0 = (const float4*)(g_dout + (size_t)g_pos[2 * t] * HID) + h;
    const float4* r1 = (const float4*)(g_dout + (size_t)g_pos[2 * t + 1] * HID) + h;
    float4 a = *r0, b = *r1;
    out[i] = make_float4(a.x + b.x, a.y + b.y, a.z + b.z, a.w + b.w);
}

// ---------------- GEMM 1: gate+up, C=128x(128g|128u), 4-stage, 512thr ----
__global__ __launch_bounds__(512, 1)
void gemm_gu_mma(void) {
    const int e   = blockIdx.z;
    const int cnt = g_counts[e];
    const int m0  = blockIdx.y * 128;
    if (m0 >= cnt) return;
    const int base = g_offsets[e];
    const int n0   = blockIdx.x * 128;

    extern __shared__ char smem[];
    const uint32_t sb = smem_u32(smem);
    int*   sTok = (int*)smem;
    float* sW   = (float*)(smem + 512);

    const int tid  = threadIdx.x;
    const int wid  = tid >> 5;
    const int lane = tid & 31;

    if (tid < 128) {
        int m = m0 + tid;
        int r = base + (m < cnt ? m : cnt - 1);
        sTok[tid] = g_token[r];
        sW[tid]   = (m < cnt) ? g_weight[r] : 0.f;
    }
    __syncthreads();

    const int lrow  = tid >> 1;
    const int lhalf = tid & 1;
    const int ge0 = lhalf * 16, ge1 = lhalf * 16 + 8;
    const __nv_bfloat16* aRowH = g_xh + (size_t)sTok[lrow & 127] * HID;
    const __nv_bfloat16* aRowL = g_xl + (size_t)sTok[lrow & 127] * HID;
    const uint32_t soA0 = swz(lrow & 127, lhalf * 2);
    const uint32_t soA1 = swz(lrow & 127, lhalf * 2 + 1);
    const __nv_bfloat16* bRowH = (lrow < 128)
        ? g_gh + ((size_t)e * INTER_ + n0 + lrow) * HID
        : g_uh + ((size_t)e * INTER_ + n0 + lrow - 128) * HID;
    const __nv_bfloat16* bRowL = (lrow < 128)
        ? g_gl + ((size_t)e * INTER_ + n0 + lrow) * HID
        : g_ul + ((size_t)e * INTER_ + n0 + lrow - 128) * HID;
    const uint32_t soB0 = swz(lrow, lhalf * 2);
    const uint32_t soB1 = swz(lrow, lhalf * 2 + 1);
    const bool doA = (tid < 256);

    const int wm = wid >> 3, wn = wid & 7;
    const int g  = lane >> 2, t4 = lane & 3;
    const int lg = lane >> 3, lr7 = lane & 7;

    int rowA[4], xA[4];
    #pragma unroll
    for (int mt = 0; mt < 4; mt++) {
        rowA[mt] = wm * 64 + mt * 16 + (lg & 1) * 8 + lr7;
        xA[mt]   = (rowA[mt] >> 1) & 3;
    }
    int rowB[2], xB[2];
    #pragma unroll
    for (int p = 0; p < 2; p++) {
        rowB[p] = wn * 32 + (2 * p + (lg >> 1)) * 8 + lr7;
        xB[p]   = (rowB[p] >> 1) & 3;
    }

    float acc[4][4][4];
    #pragma unroll
    for (int i = 0; i < 4; i++)
        #pragma unroll
        for (int j = 0; j < 4; j++)
            #pragma unroll
            for (int r = 0; r < 4; r++) acc[i][j][r] = 0.f;

    const int NT = HID / KT;   // 64

    #pragma unroll
    for (int s = 0; s < 3; s++) {
        uint32_t d = sb + SLOT(s);
        int k0 = s * KT;
        if (doA) {
            CP16(d + OFF_AH + soA0, aRowH + k0 + ge0);
            CP16(d + OFF_AH + soA1, aRowH + k0 + ge1);
            CP16(d + OFF_AL + soA0, aRowL + k0 + ge0);
            CP16(d + OFF_AL + soA1, aRowL + k0 + ge1);
        }
        CP16(d + OFF_BH + soB0, bRowH + k0 + ge0);
        CP16(d + OFF_BH + soB1, bRowH + k0 + ge1);
        CP16(d + OFF_BL + soB0, bRowL + k0 + ge0);
        CP16(d + OFF_BL + soB1, bRowL + k0 + ge1);
        CP_COMMIT();
    }

    int slot = 0, wslot = 3;
    for (int t = 0; t < NT; t++) {
        if (t + 2 < NT)      { CP_WAIT(2); }
        else if (t + 1 < NT) { CP_WAIT(1); }
        else                 { CP_WAIT(0); }
        __syncthreads();
        if (t + 3 < NT) {
            uint32_t d = sb + SLOT(wslot);
            int k0 = (t + 3) * KT;
            if (doA) {
                CP16(d + OFF_AH + soA0, aRowH + k0 + ge0);
                CP16(d + OFF_AH + soA1, aRowH + k0 + ge1);
                CP16(d + OFF_AL + soA0, aRowL + k0 + ge0);
                CP16(d + OFF_AL + soA1, aRowL + k0 + ge1);
            }
            CP16(d + OFF_BH + soB0, bRowH + k0 + ge0);
            CP16(d + OFF_BH + soB1, bRowH + k0 + ge1);
            CP16(d + OFF_BL + soB0, bRowL + k0 + ge0);
            CP16(d + OFF_BL + soB1, bRowL + k0 + ge1);
            CP_COMMIT();
        }
        const uint32_t sa = sb + SLOT(slot);
        #pragma unroll
        for (int ks = 0; ks < 2; ks++) {
            const int cA = ks * 2 + (lg >> 1);
            const int cB = ks * 2 + (lg & 1);
            uint32_t bh[2][4], bl[2][4];
            #pragma unroll
            for (int p = 0; p < 2; p++) {
                uint32_t ab = sa + OFF_BH + (rowB[p] << 6) + (((cB ^ xB[p])) << 4);
                ldm_x4(bh[p], ab);
                ldm_x4(bl[p], ab + PLANE_B);
            }
            #pragma unroll
            for (int mt = 0; mt < 4; mt++) {
                uint32_t aa = sa + OFF_AH + (rowA[mt] << 6) + (((cA ^ xA[mt])) << 4);
                uint32_t ah[4], al[4];
                ldm_x4(ah, aa);
                ldm_x4(al, aa + PLANE_A);
                #pragma unroll
                for (int nt = 0; nt < 4; nt++) {
                    const uint32_t* BH = &bh[nt >> 1][(nt & 1) * 2];
                    const uint32_t* BL = &bl[nt >> 1][(nt & 1) * 2];
                    mma_bf16(acc[mt][nt], al, BH);
                    mma_bf16(acc[mt][nt], ah, BL);
                    mma_bf16(acc[mt][nt], ah, BH);
                }
            }
        }
        slot  = (slot  == 3) ? 0 : slot + 1;
        wslot = (wslot == 3) ? 0 : wslot + 1;
    }
    __syncthreads();

    float* Cs = (float*)(smem + SM_BUF);
    #pragma unroll
    for (int mt = 0; mt < 4; mt++) {
        #pragma unroll
        for (int nt = 0; nt < 4; nt++) {
            int row = wm * 64 + mt * 16 + g;
            int col = wn * 32 + nt * 8 + t4 * 2;
            *reinterpret_cast<float2*>(&Cs[row * CS_STRIDE + col]) =
                make_float2(acc[mt][nt][0], acc[mt][nt][1]);
            *reinterpret_cast<float2*>(&Cs[(row + 8) * CS_STRIDE + col]) =
                make_float2(acc[mt][nt][2], acc[mt][nt][3]);
        }
    }
    __syncthreads();

    const int jj = (tid & 31) * 4;
    const int rb = (tid >> 5) * 8;
    #pragma unroll
    for (int mm = 0; mm < 8; mm++) {
        int m = rb + mm;
        if (m0 + m >= cnt) continue;
        float w = sW[m];
        float4 gv = *reinterpret_cast<const float4*>(&Cs[m * CS_STRIDE + jj]);
        float4 uv = *reinterpret_cast<const float4*>(&Cs[m * CS_STRIDE + 128 + jj]);
        float o0 = (gv.x / (1.f + __expf(-gv.x))) * uv.x * w;
        float o1 = (gv.y / (1.f + __expf(-gv.y))) * uv.y * w;
        float o2 = (gv.z / (1.f + __expf(-gv.z))) * uv.z * w;
        float o3 = (gv.w / (1.f + __expf(-gv.w))) * uv.w * w;
        float r0, r1, r2, r3;
        uint2 H, L;
        H.x = packhl(o0, o1, r0, r1);
        H.y = packhl(o2, o3, r2, r3);
        L.x = packlo(r0, r1);
        L.y = packlo(r2, r3);
        size_t idx = (size_t)(base + m0 + m) * INTER_ + n0 + jj;
        *reinterpret_cast<uint2*>(&g_ih[idx]) = H;
        *reinterpret_cast<uint2*>(&g_il[idx]) = L;
    }
}

// ---------------- GEMM 2: down, 256thr (8 warps 2x4), C=64x128, 3-stage, 3 CTA/SM
__global__ __launch_bounds__(256, 3)
void gemm_down_mma(void) {
    const int e   = blockIdx.z;
    const int cnt = g_counts[e];
    const int m0  = blockIdx.y * 64;
    if (m0 >= cnt) return;
    const int base = g_offsets[e];
    const int n0   = blockIdx.x * 128;

    extern __shared__ char smem[];
    const uint32_t sb = smem_u32(smem);

    const int tid  = threadIdx.x;
    const int wid  = tid >> 5;
    const int lane = tid & 31;

    // loaders: A 64 rows (1 chunk/plane per thread), B 128 rows (2 chunks/plane)
    const int tAr = tid >> 2;          // 0..63
    const int tAc = tid & 3;
    const int tBr = tid >> 1;          // 0..127
    const int tBc = (tid & 1) * 2;
    int ar = base + m0 + tAr; if (ar > NSLOT - 1) ar = NSLOT - 1;
    const __nv_bfloat16* aRowH = g_ih + (size_t)ar * INTER_;
    const __nv_bfloat16* aRowL = g_il + (size_t)ar * INTER_;
    const __nv_bfloat16* bRowH = g_dh + ((size_t)e * HID + n0 + tBr) * INTER_;
    const __nv_bfloat16* bRowL = g_dl + ((size_t)e * HID + n0 + tBr) * INTER_;
    const uint32_t soA  = swz(tAr, tAc);
    const int      geA  = tAc * 8;
    const uint32_t soB0 = swz(tBr, tBc);
    const uint32_t soB1 = swz(tBr, tBc + 1);
    const int      geB0 = tBc * 8, geB1 = tBc * 8 + 8;

    const int wm = wid >> 2, wn = wid & 3;      // 2 x 4 warps, warp 32x32
    const int g  = lane >> 2, t4 = lane & 3;
    const int lg = lane >> 3, lr7 = lane & 7;

    int rowA[2], xA[2];
    #pragma unroll
    for (int mt = 0; mt < 2; mt++) {
        rowA[mt] = wm * 32 + mt * 16 + (lg & 1) * 8 + lr7;
        xA[mt]   = (rowA[mt] >> 1) & 3;
    }
    int rowB[2], xB[2];
    #pragma unroll
    for (int p = 0; p < 2; p++) {
        rowB[p] = wn * 32 + (2 * p + (lg >> 1)) * 8 + lr7;
        xB[p]   = (rowB[p] >> 1) & 3;
    }

    float acc[2][4][4];
    #pragma unroll
    for (int i = 0; i < 2; i++)
        #pragma unroll
        for (int j = 0; j < 4; j++)
            #pragma unroll
            for (int r = 0; r < 4; r++) acc[i][j][r] = 0.f;

    const int NT = INTER_ / KT;   // 32

    #pragma unroll
    for (int s = 0; s < 2; s++) {
        uint32_t d = sb + DSLOT(s);
        int k0 = s * KT;
        CP16(d + D_AH + soA,  aRowH + k0 + geA);
        CP16(d + D_AL + soA,  aRowL + k0 + geA);
        CP16(d + D_BH + soB0, bRowH + k0 + geB0);
        CP16(d + D_BH + soB1, bRowH + k0 + geB1);
        CP16(d + D_BL + soB0, bRowL + k0 + geB0);
        CP16(d + D_BL + soB1, bRowL + k0 + geB1);
        CP_COMMIT();
    }

    int slot = 0, wslot = 2;
    for (int t = 0; t < NT; t++) {
        if (t < NT - 1) { CP_WAIT(1); } else { CP_WAIT(0); }
        __syncthreads();
        if (t + 2 < NT) {
            uint32_t d = sb + DSLOT(wslot);
            int k0 = (t + 2) * KT;
            CP16(d + D_AH + soA,  aRowH + k0 + geA);
            CP16(d + D_AL + soA,  aRowL + k0 + geA);
            CP16(d + D_BH + soB0, bRowH + k0 + geB0);
            CP16(d + D_BH + soB1, bRowH + k0 + geB1);
            CP16(d + D_BL + soB0, bRowL + k0 + geB0);
            CP16(d + D_BL + soB1, bRowL + k0 + geB1);
            CP_COMMIT();
        }
        const uint32_t sa = sb + DSLOT(slot);
        #pragma unroll
        for (int ks = 0; ks < 2; ks++) {
            const int cA = ks * 2 + (lg >> 1);
            const int cB = ks * 2 + (lg & 1);
            uint32_t bh[2][4], bl[2][4];
            #pragma unroll
            for (int p = 0; p < 2; p++) {
                uint32_t ab = sa + D_BH + (rowB[p] << 6) + (((cB ^ xB[p])) << 4);
                ldm_x4(bh[p], ab);
                ldm_x4(bl[p], ab + DPB);
            }
            #pragma unroll
            for (int mt = 0; mt < 2; mt++) {
                uint32_t aa = sa + D_AH + (rowA[mt] << 6) + (((cA ^ xA[mt])) << 4);
                uint32_t ah[4], al[4];
                ldm_x4(ah, aa);
                ldm_x4(al, aa + DPA);
                #pragma unroll
                for (int nt = 0; nt < 4; nt++) {
                    const uint32_t* BH = &bh[nt >> 1][(nt & 1) * 2];
                    const uint32_t* BL = &bl[nt >> 1][(nt & 1) * 2];
                    mma_bf16(acc[mt][nt], al, BH);
                    mma_bf16(acc[mt][nt], ah, BL);
                    mma_bf16(acc[mt][nt], ah, BH);
                }
            }
        }
        slot  = (slot  == 2) ? 0 : slot + 1;
        wslot = (wslot == 2) ? 0 : wslot + 1;
    }

    // dense store to g_dout (sorted slot order)
    #pragma unroll
    for (int mt = 0; mt < 2; mt++) {
        int row0 = wm * 32 + mt * 16 + g;
        int row1 = row0 + 8;
        bool v0 = (m0 + row0 < cnt);
        bool v1 = (m0 + row1 < cnt);
        float* o0 = g_dout + (size_t)(base + m0 + row0) * HID + n0;
        float* o1 = g_dout + (size_t)(base + m0 + row1) * HID + n0;
        #pragma unroll
        for (int nt = 0; nt < 4; nt++) {
            int col = wn * 32 + nt * 8 + t4 * 2;
            if (v0) *reinterpret_cast<float2*>(&o0[col]) =
                        make_float2(acc[mt][nt][0], acc[mt][nt][1]);
            if (v1) *reinterpret_cast<float2*>(&o1[col]) =
                        make_float2(acc[mt][nt][2], acc[mt][nt][3]);
        }
    }
}

// ---------------- stream/event handles ----------------
static cudaStream_t g_s2 = nullptr;
static cudaEvent_t  g_evF = nullptr, g_evJ = nullptr;
static struct _StreamInit {
    _StreamInit() {
        if (cudaStreamCreateWithFlags(&g_s2, cudaStreamNonBlocking) != cudaSuccess) g_s2 = nullptr;
        if (cudaEventCreateWithFlags(&g_evF, cudaEventDisableTiming) != cudaSuccess) g_evF = nullptr;
        if (cudaEventCreateWithFlags(&g_evJ, cudaEventDisableTiming) != cudaSuccess) g_evJ = nullptr;
    }
} g_stream_init;

// ---------------- launch ----------------
extern "C" void kernel_launch(void* const* d_in, const int* in_sizes, int n_in,
                              void* d_out, int out_size) {
    const float* x    = (const float*)d_in[0];
    const int*   idxw = (const int*)d_in[1];
    const float* wts  = (const float*)d_in[2];
    const float* gate = (const float*)d_in[3];
    const float* up   = (const float*)d_in[4];
    const float* down = (const float*)d_in[5];
    float* out = (float*)d_out;

    cudaFuncSetAttribute(gemm_gu_mma,   cudaFuncAttributeMaxDynamicSharedMemorySize, GU_SMEM);
    cudaFuncSetAttribute(gemm_down_mma, cudaFuncAttributeMaxDynamicSharedMemorySize, DN_SMEM);

    __nv_bfloat16 *xh, *xl, *gh, *gl, *uh, *ul, *dh, *dl;
    cudaGetSymbolAddress((void**)&xh, g_xh);
    cudaGetSymbolAddress((void**)&xl, g_xl);
    cudaGetSymbolAddress((void**)&gh, g_gh);
    cudaGetSymbolAddress((void**)&gl, g_gl);
    cudaGetSymbolAddress((void**)&uh, g_uh);
    cudaGetSymbolAddress((void**)&ul, g_ul);
    cudaGetSymbolAddress((void**)&dh, g_dh);
    cudaGetSymbolAddress((void**)&dl, g_dl);

    const int nw = NEXP * INTER_ * HID / 4;
    const bool use_streams = (g_s2 && g_evF && g_evJ);

    if (use_streams) {
        cudaEventRecord(g_evF, 0);
        cudaStreamWaitEvent(g_s2, g_evF, 0);
        split_down_k<<<(nw + 255) / 256, 256, 0, g_s2>>>(
            (const float4*)down, (uint2*)dh, (uint2*)dl, nw);
        cudaEventRecord(g_evJ, g_s2);
    } else {
        split_down_k<<<(nw + 255) / 256, 256>>>(
            (const float4*)down, (uint2*)dh, (uint2*)dl, nw);
    }

    route_kernel<<<1, 256>>>(idxw, wts);
    {
        int total = 2 * nw + NTOK * HID / 4;
        split_xgu<<<(total + 255) / 256, 256>>>(
            (const float4*)x, (const float4*)gate, (const float4*)up,
            (uint2*)xh, (uint2*)xl, (uint2*)gh, (uint2*)gl, (uint2*)uh, (uint2*)ul);
    }
    {
        dim3 grid(INTER_ / 128, NSLOT / 128, NEXP);
        gemm_gu_mma<<<grid, 512, GU_SMEM>>>();
    }
    if (use_streams) {
        cudaStreamWaitEvent(0, g_evJ, 0);
    }
    {
        dim3 grid(HID / 128, NSLOT / 64, NEXP);
        gemm_down_mma<<<grid, 256, DN_SMEM>>>();
    }
    {
        int ng = NTOK * HID / 4;
        gather_kernel<<<(ng + 255) / 256, 256>>>((float4*)out);
    }
}

// round 14
// speedup vs baseline: 1.0270x; 1.0223x over previous
#include <cuda_runtime.h>
#include <cuda_bf16.h>
#include <math.h>
#include <stdint.h>

// Problem constants
#define NTOK   2048
#define HID    2048
#define INTER_ 1024
#define NEXP   8
#define TOPK   2
#define NSLOT  (NTOK * TOPK)

// ---- gu kernel: 512 thr, C=128x256, 4-stage ----
#define KT      32
#define PLANE_A 8192
#define PLANE_B 16384
#define STAGE   (2 * PLANE_A + 2 * PLANE_B)
#define SM_BUF  1024
#define SLOT(s)   (SM_BUF + (s) * STAGE)
#define OFF_AH  0
#define OFF_AL  PLANE_A
#define OFF_BH  (2 * PLANE_A)
#define OFF_BL  (2 * PLANE_A + PLANE_B)
#define GU_SMEM (SM_BUF + 4 * STAGE)         // 197632
#define CS_STRIDE 264

// ---- down kernel: 256 thr, C=128x128, 3-stage, 2 CTA/SM ----
#define DPLANE  8192
#define DSTAGE  (4 * DPLANE)
#define DSLOT(s) (SM_BUF + (s) * DSTAGE)
#define DN_SMEM (SM_BUF + 3 * DSTAGE)        // 99328

// -------- device scratch --------
__device__ int   g_counts[NEXP];
__device__ int   g_offsets[NEXP];
__device__ int   g_token[NSLOT];
__device__ float g_weight[NSLOT];
__device__ __nv_bfloat16 g_xh[(size_t)NTOK * HID];
__device__ __nv_bfloat16 g_xl[(size_t)NTOK * HID];
__device__ __nv_bfloat16 g_gh[(size_t)NEXP * INTER_ * HID];
__device__ __nv_bfloat16 g_gl[(size_t)NEXP * INTER_ * HID];
__device__ __nv_bfloat16 g_uh[(size_t)NEXP * INTER_ * HID];
__device__ __nv_bfloat16 g_ul[(size_t)NEXP * INTER_ * HID];
__device__ __nv_bfloat16 g_dh[(size_t)NEXP * HID * INTER_];
__device__ __nv_bfloat16 g_dl[(size_t)NEXP * HID * INTER_];
__device__ __nv_bfloat16 g_ih[(size_t)NSLOT * INTER_];
__device__ __nv_bfloat16 g_il[(size_t)NSLOT * INTER_];

// ---------------- helpers ----------------
__device__ __forceinline__ uint32_t smem_u32(const void* p) {
    uint32_t a;
    asm("{ .reg .u64 t; cvta.to.shared.u64 t, %1; cvt.u32.u64 %0, t; }" : "=r"(a) : "l"(p));
    return a;
}
#define CP16(sm, gm) asm volatile("cp.async.cg.shared.global [%0], [%1], 16;" :: "r"(sm), "l"(gm))
#define CP_COMMIT()  asm volatile("cp.async.commit_group;" ::: "memory")
#define CP_WAIT(n)   asm volatile("cp.async.wait_group %0;" :: "n"(n) : "memory")

__device__ __forceinline__ void mma_bf16(float* c, const uint32_t* a, const uint32_t* b) {
    asm volatile(
        "mma.sync.aligned.m16n8k16.row.col.f32.bf16.bf16.f32 "
        "{%0,%1,%2,%3}, {%4,%5,%6,%7}, {%8,%9}, {%0,%1,%2,%3};\n"
        : "+f"(c[0]), "+f"(c[1]), "+f"(c[2]), "+f"(c[3])
        : "r"(a[0]), "r"(a[1]), "r"(a[2]), "r"(a[3]), "r"(b[0]), "r"(b[1]));
}
__device__ __forceinline__ void ldm_x4(uint32_t* r, uint32_t addr) {
    asm volatile("ldmatrix.sync.aligned.m8n8.x4.shared.b16 {%0,%1,%2,%3}, [%4];"
        : "=r"(r[0]), "=r"(r[1]), "=r"(r[2]), "=r"(r[3]) : "r"(addr));
}
__device__ __forceinline__ uint32_t swz(int row, int chunk) {
    return (uint32_t)((row << 6) + (((chunk ^ ((row >> 1) & 3))) << 4));
}
__device__ __forceinline__ uint32_t packhl(float a, float b, float& ra, float& rb) {
    __nv_bfloat16 ha = __float2bfloat16(a);
    __nv_bfloat16 hb = __float2bfloat16(b);
    ra = a - __bfloat162float(ha);
    rb = b - __bfloat162float(hb);
    __nv_bfloat162 p = __halves2bfloat162(ha, hb);
    return *reinterpret_cast<uint32_t*>(&p);
}
__device__ __forceinline__ uint32_t packlo(float a, float b) {
    __nv_bfloat162 p = __halves2bfloat162(__float2bfloat16(a), __float2bfloat16(b));
    return *reinterpret_cast<uint32_t*>(&p);
}

// ---------------- splits ----------------
__global__ void split_xgu(const float4* __restrict__ xs,
                          const float4* __restrict__ gs,
                          const float4* __restrict__ us,
                          uint2* __restrict__ xh, uint2* __restrict__ xl,
                          uint2* __restrict__ gh, uint2* __restrict__ gl,
                          uint2* __restrict__ uh, uint2* __restrict__ ul) {
    const int nw = NEXP * INTER_ * HID / 4;
    const int nx = NTOK * HID / 4;
    int i = blockIdx.x * blockDim.x + threadIdx.x;
    const float4* src; uint2 *H, *L; int j;
    if (i < nw)               { src = gs; H = gh; L = gl; j = i; }
    else if (i < 2 * nw)      { src = us; H = uh; L = ul; j = i - nw; }
    else if (i < 2 * nw + nx) { src = xs; H = xh; L = xl; j = i - 2 * nw; }
    else return;
    float4 v = src[j];
    float rx, ry, rz, rw;
    uint2 Hv, Lv;
    Hv.x = packhl(v.x, v.y, rx, ry);
    Hv.y = packhl(v.z, v.w, rz, rw);
    Lv.x = packlo(rx, ry);
    Lv.y = packlo(rz, rw);
    H[j] = Hv;
    L[j] = Lv;
}
__global__ void split_down_k(const float4* __restrict__ ds,
                             uint2* __restrict__ dh, uint2* __restrict__ dl, int n4) {
    int i = blockIdx.x * blockDim.x + threadIdx.x;
    if (i >= n4) return;
    float4 v = ds[i];
    float rx, ry, rz, rw;
    uint2 Hv, Lv;
    Hv.x = packhl(v.x, v.y, rx, ry);
    Hv.y = packhl(v.z, v.w, rz, rw);
    Lv.x = packlo(rx, ry);
    Lv.y = packlo(rz, rw);
    dh[i] = Hv;
    dl[i] = Lv;
}

__global__ void zero_kernel(float4* __restrict__ out, int n4) {
    int i = blockIdx.x * blockDim.x + threadIdx.x;
    if (i < n4) out[i] = make_float4(0.f, 0.f, 0.f, 0.f);
}

// ---------------- routing ----------------
__global__ void route_kernel(const int* __restrict__ idxw,
                             const float* __restrict__ wts) {
    __shared__ int cnt[NEXP], off[NEXP], cur[NEXP];
    __shared__ int not64;
    int tid = threadIdx.x;
    if (tid < NEXP) { cnt[tid] = 0; cur[tid] = 0; }
    if (tid == 0) not64 = 0;
    __syncthreads();
    int any = 0;
    for (int i = 2 * tid + 1; i < NSLOT; i += 2 * blockDim.x) any |= idxw[i];
    if (any) atomicOr(&not64, 1);
    __syncthreads();
    const int is64 = !not64;
    for (int s = tid; s < NSLOT; s += blockDim.x) {
        int e = is64 ? idxw[2 * s] : idxw[s];
        atomicAdd(&cnt[e], 1);
    }
    __syncthreads();
    if (tid == 0) {
        int acc = 0;
        for (int e = 0; e < NEXP; e++) {
            off[e] = acc; g_offsets[e] = acc; g_counts[e] = cnt[e];
            acc += cnt[e];
        }
    }
    __syncthreads();
    for (int s = tid; s < NSLOT; s += blockDim.x) {
        int e = is64 ? idxw[2 * s] : idxw[s];
        int p = off[e] + atomicAdd(&cur[e], 1);
        g_token[p]  = s >> 1;
        g_weight[p] = wts[s];
    }
}

// ---------------- GEMM 1: gate+up, C=128x(128g|128u), 4-stage, 512thr ----
__global__ __launch_bounds__(512, 1)
void gemm_gu_mma(void) {
    const int e   = blockIdx.z;
    const int cnt = g_counts[e];
    const int m0  = blockIdx.y * 128;
    if (m0 >= cnt) return;
    const int base = g_offsets[e];
    const int n0   = blockIdx.x * 128;

    extern __shared__ char smem[];
    const uint32_t sb = smem_u32(smem);
    int*   sTok = (int*)smem;
    float* sW   = (float*)(smem + 512);

    const int tid  = threadIdx.x;
    const int wid  = tid >> 5;
    const int lane = tid & 31;

    if (tid < 128) {
        int m = m0 + tid;
        int r = base + (m < cnt ? m : cnt - 1);
        sTok[tid] = g_token[r];
        sW[tid]   = (m < cnt) ? g_weight[r] : 0.f;
    }
    __syncthreads();

    const int lrow  = tid >> 1;
    const int lhalf = tid & 1;
    const int ge0 = lhalf * 16, ge1 = lhalf * 16 + 8;
    const __nv_bfloat16* aRowH = g_xh + (size_t)sTok[lrow & 127] * HID;
    const __nv_bfloat16* aRowL = g_xl + (size_t)sTok[lrow & 127] * HID;
    const uint32_t soA0 = swz(lrow & 127, lhalf * 2);
    const uint32_t soA1 = swz(lrow & 127, lhalf * 2 + 1);
    const __nv_bfloat16* bRowH = (lrow < 128)
        ? g_gh + ((size_t)e * INTER_ + n0 + lrow) * HID
        : g_uh + ((size_t)e * INTER_ + n0 + lrow - 128) * HID;
    const __nv_bfloat16* bRowL = (lrow < 128)
        ? g_gl + ((size_t)e * INTER_ + n0 + lrow) * HID
        : g_ul + ((size_t)e * INTER_ + n0 + lrow - 128) * HID;
    const uint32_t soB0 = swz(lrow, lhalf * 2);
    const uint32_t soB1 = swz(lrow, lhalf * 2 + 1);
    const bool doA = (tid < 256);

    const int wm = wid >> 3, wn = wid & 7;
    const int g  = lane >> 2, t4 = lane & 3;
    const int lg = lane >> 3, lr7 = lane & 7;

    int rowA[4], xA[4];
    #pragma unroll
    for (int mt = 0; mt < 4; mt++) {
        rowA[mt] = wm * 64 + mt * 16 + (lg & 1) * 8 + lr7;
        xA[mt]   = (rowA[mt] >> 1) & 3;
    }
    int rowB[2], xB[2];
    #pragma unroll
    for (int p = 0; p < 2; p++) {
        rowB[p] = wn * 32 + (2 * p + (lg >> 1)) * 8 + lr7;
        xB[p]   = (rowB[p] >> 1) & 3;
    }

    float acc[4][4][4];
    #pragma unroll
    for (int i = 0; i < 4; i++)
        #pragma unroll
        for (int j = 0; j < 4; j++)
            #pragma unroll
            for (int r = 0; r < 4; r++) acc[i][j][r] = 0.f;

    const int NT = HID / KT;   // 64

    #pragma unroll
    for (int s = 0; s < 3; s++) {
        uint32_t d = sb + SLOT(s);
        int k0 = s * KT;
        if (doA) {
            CP16(d + OFF_AH + soA0, aRowH + k0 + ge0);
            CP16(d + OFF_AH + soA1, aRowH + k0 + ge1);
            CP16(d + OFF_AL + soA0, aRowL + k0 + ge0);
            CP16(d + OFF_AL + soA1, aRowL + k0 + ge1);
        }
        CP16(d + OFF_BH + soB0, bRowH + k0 + ge0);
        CP16(d + OFF_BH + soB1, bRowH + k0 + ge1);
        CP16(d + OFF_BL + soB0, bRowL + k0 + ge0);
        CP16(d + OFF_BL + soB1, bRowL + k0 + ge1);
        CP_COMMIT();
    }

    int slot = 0, wslot = 3;
    for (int t = 0; t < NT; t++) {
        if (t + 2 < NT)      { CP_WAIT(2); }
        else if (t + 1 < NT) { CP_WAIT(1); }
        else                 { CP_WAIT(0); }
        __syncthreads();
        if (t + 3 < NT) {
            uint32_t d = sb + SLOT(wslot);
            int k0 = (t + 3) * KT;
            if (doA) {
                CP16(d + OFF_AH + soA0, aRowH + k0 + ge0);
                CP16(d + OFF_AH + soA1, aRowH + k0 + ge1);
                CP16(d + OFF_AL + soA0, aRowL + k0 + ge0);
                CP16(d + OFF_AL + soA1, aRowL + k0 + ge1);
            }
            CP16(d + OFF_BH + soB0, bRowH + k0 + ge0);
            CP16(d + OFF_BH + soB1, bRowH + k0 + ge1);
            CP16(d + OFF_BL + soB0, bRowL + k0 + ge0);
            CP16(d + OFF_BL + soB1, bRowL + k0 + ge1);
            CP_COMMIT();
        }
        const uint32_t sa = sb + SLOT(slot);
        #pragma unroll
        for (int ks = 0; ks < 2; ks++) {
            const int cA = ks * 2 + (lg >> 1);
            const int cB = ks * 2 + (lg & 1);
            uint32_t bh[2][4], bl[2][4];
            #pragma unroll
            for (int p = 0; p < 2; p++) {
                uint32_t ab = sa + OFF_BH + (rowB[p] << 6) + (((cB ^ xB[p])) << 4);
                ldm_x4(bh[p], ab);
                ldm_x4(bl[p], ab + PLANE_B);
            }
            #pragma unroll
            for (int mt = 0; mt < 4; mt++) {
                uint32_t aa = sa + OFF_AH + (rowA[mt] << 6) + (((cA ^ xA[mt])) << 4);
                uint32_t ah[4], al[4];
                ldm_x4(ah, aa);
                ldm_x4(al, aa + PLANE_A);
                #pragma unroll
                for (int nt = 0; nt < 4; nt++) {
                    const uint32_t* BH = &bh[nt >> 1][(nt & 1) * 2];
                    const uint32_t* BL = &bl[nt >> 1][(nt & 1) * 2];
                    mma_bf16(acc[mt][nt], al, BH);
                    mma_bf16(acc[mt][nt], ah, BL);
                    mma_bf16(acc[mt][nt], ah, BH);
                }
            }
        }
        slot  = (slot  == 3) ? 0 : slot + 1;
        wslot = (wslot == 3) ? 0 : wslot + 1;
    }
    __syncthreads();

    float* Cs = (float*)(smem + SM_BUF);
    #pragma unroll
    for (int mt = 0; mt < 4; mt++) {
        #pragma unroll
        for (int nt = 0; nt < 4; nt++) {
            int row = wm * 64 + mt * 16 + g;
            int col = wn * 32 + nt * 8 + t4 * 2;
            *reinterpret_cast<float2*>(&Cs[row * CS_STRIDE + col]) =
                make_float2(acc[mt][nt][0], acc[mt][nt][1]);
            *reinterpret_cast<float2*>(&Cs[(row + 8) * CS_STRIDE + col]) =
                make_float2(acc[mt][nt][2], acc[mt][nt][3]);
        }
    }
    __syncthreads();

    const int jj = (tid & 31) * 4;
    const int rb = (tid >> 5) * 8;
    #pragma unroll
    for (int mm = 0; mm < 8; mm++) {
        int m = rb + mm;
        if (m0 + m >= cnt) continue;
        float w = sW[m];
        float4 gv = *reinterpret_cast<const float4*>(&Cs[m * CS_STRIDE + jj]);
        float4 uv = *reinterpret_cast<const float4*>(&Cs[m * CS_STRIDE + 128 + jj]);
        float o0 = (gv.x / (1.f + __expf(-gv.x))) * uv.x * w;
        float o1 = (gv.y / (1.f + __expf(-gv.y))) * uv.y * w;
        float o2 = (gv.z / (1.f + __expf(-gv.z))) * uv.z * w;
        float o3 = (gv.w / (1.f + __expf(-gv.w))) * uv.w * w;
        float r0, r1, r2, r3;
        uint2 H, L;
        H.x = packhl(o0, o1, r0, r1);
        H.y = packhl(o2, o3, r2, r3);
        L.x = packlo(r0, r1);
        L.y = packlo(r2, r3);
        size_t idx = (size_t)(base + m0 + m) * INTER_ + n0 + jj;
        *reinterpret_cast<uint2*>(&g_ih[idx]) = H;
        *reinterpret_cast<uint2*>(&g_il[idx]) = L;
    }
}

// ---------------- GEMM 2: down, 256thr, 128x128, 3-stage + atomic scatter --
__global__ __launch_bounds__(256, 2)
void gemm_down_mma(float* __restrict__ out) {
    const int e   = blockIdx.z;
    const int cnt = g_counts[e];
    const int m0  = blockIdx.y * 128;
    if (m0 >= cnt) return;
    const int base = g_offsets[e];
    const int n0   = blockIdx.x * 128;

    extern __shared__ char smem[];
    const uint32_t sb = smem_u32(smem);

    const int tid  = threadIdx.x;
    const int wid  = tid >> 5;
    const int lane = tid & 31;

    const int lrow  = tid >> 1;
    const int lhalf = tid & 1;
    int ar = base + m0 + lrow; if (ar > NSLOT - 1) ar = NSLOT - 1;
    const __nv_bfloat16* aRowH = g_ih + (size_t)ar * INTER_;
    const __nv_bfloat16* aRowL = g_il + (size_t)ar * INTER_;
    const __nv_bfloat16* bRowH = g_dh + ((size_t)e * HID + n0 + lrow) * INTER_;
    const __nv_bfloat16* bRowL = g_dl + ((size_t)e * HID + n0 + lrow) * INTER_;
    const uint32_t so0 = swz(lrow, lhalf * 2);
    const uint32_t so1 = swz(lrow, lhalf * 2 + 1);
    const int ge0 = lhalf * 16, ge1 = lhalf * 16 + 8;

    const int wm = wid >> 2, wn = wid & 3;
    const int g  = lane >> 2, t4 = lane & 3;
    const int lg = lane >> 3, lr7 = lane & 7;

    int rowA[4], xA[4];
    #pragma unroll
    for (int mt = 0; mt < 4; mt++) {
        rowA[mt] = wm * 64 + mt * 16 + (lg & 1) * 8 + lr7;
        xA[mt]   = (rowA[mt] >> 1) & 3;
    }
    int rowB[2], xB[2];
    #pragma unroll
    for (int p = 0; p < 2; p++) {
        rowB[p] = wn * 32 + (2 * p + (lg >> 1)) * 8 + lr7;
        xB[p]   = (rowB[p] >> 1) & 3;
    }

    float acc[4][4][4];
    #pragma unroll
    for (int i = 0; i < 4; i++)
        #pragma unroll
        for (int j = 0; j < 4; j++)
            #pragma unroll
            for (int r = 0; r < 4; r++) acc[i][j][r] = 0.f;

    const int NT = INTER_ / KT;   // 32

    #pragma unroll
    for (int s = 0; s < 2; s++) {
        uint32_t d = sb + DSLOT(s);
        int k0 = s * KT;
        CP16(d + so0,              aRowH + k0 + ge0);
        CP16(d + so1,              aRowH + k0 + ge1);
        CP16(d + DPLANE + so0,     aRowL + k0 + ge0);
        CP16(d + DPLANE + so1,     aRowL + k0 + ge1);
        CP16(d + 2 * DPLANE + so0, bRowH + k0 + ge0);
        CP16(d + 2 * DPLANE + so1, bRowH + k0 + ge1);
        CP16(d + 3 * DPLANE + so0, bRowL + k0 + ge0);
        CP16(d + 3 * DPLANE + so1, bRowL + k0 + ge1);
        CP_COMMIT();
    }

    int slot = 0, wslot = 2;
    for (int t = 0; t < NT; t++) {
        if (t < NT - 1) { CP_WAIT(1); } else { CP_WAIT(0); }
        __syncthreads();
        if (t + 2 < NT) {
            uint32_t d = sb + DSLOT(wslot);
            int k0 = (t + 2) * KT;
            CP16(d + so0,              aRowH + k0 + ge0);
            CP16(d + so1,              aRowH + k0 + ge1);
            CP16(d + DPLANE + so0,     aRowL + k0 + ge0);
            CP16(d + DPLANE + so1,     aRowL + k0 + ge1);
            CP16(d + 2 * DPLANE + so0, bRowH + k0 + ge0);
            CP16(d + 2 * DPLANE + so1, bRowH + k0 + ge1);
            CP16(d + 3 * DPLANE + so0, bRowL + k0 + ge0);
            CP16(d + 3 * DPLANE + so1, bRowL + k0 + ge1);
            CP_COMMIT();
        }
        const uint32_t sa = sb + DSLOT(slot);
        #pragma unroll
        for (int ks = 0; ks < 2; ks++) {
            const int cA = ks * 2 + (lg >> 1);
            const int cB = ks * 2 + (lg & 1);
            uint32_t bh[2][4], bl[2][4];
            #pragma unroll
            for (int p = 0; p < 2; p++) {
                uint32_t ab = sa + 2 * DPLANE + (rowB[p] << 6) + (((cB ^ xB[p])) << 4);
                ldm_x4(bh[p], ab);
                ldm_x4(bl[p], ab + DPLANE);
            }
            #pragma unroll
            for (int mt = 0; mt < 4; mt++) {
                uint32_t aa = sa + (rowA[mt] << 6) + (((cA ^ xA[mt])) << 4);
                uint32_t ah[4], al[4];
                ldm_x4(ah, aa);
                ldm_x4(al, aa + DPLANE);
                #pragma unroll
                for (int nt = 0; nt < 4; nt++) {
                    const uint32_t* BH = &bh[nt >> 1][(nt & 1) * 2];
                    const uint32_t* BL = &bl[nt >> 1][(nt & 1) * 2];
                    mma_bf16(acc[mt][nt], al, BH);
                    mma_bf16(acc[mt][nt], ah, BL);
                    mma_bf16(acc[mt][nt], ah, BH);
                }
            }
        }
        slot  = (slot  == 2) ? 0 : slot + 1;
        wslot = (wslot == 2) ? 0 : wslot + 1;
    }

    // atomic scatter by token (duplicate-expert slots sum; out pre-zeroed)
    #pragma unroll
    for (int mt = 0; mt < 4; mt++) {
        int row0 = wm * 64 + mt * 16 + g;
        int row1 = row0 + 8;
        bool v0 = (m0 + row0 < cnt);
        bool v1 = (m0 + row1 < cnt);
        int t0 = g_token[base + m0 + (v0 ? row0 : 0)];
        int t1 = g_token[base + m0 + (v1 ? row1 : 0)];
        float* o0 = out + (size_t)t0 * HID + n0;
        float* o1 = out + (size_t)t1 * HID + n0;
        #pragma unroll
        for (int nt = 0; nt < 4; nt++) {
            int col = wn * 32 + nt * 8 + t4 * 2;
            if (v0) {
                atomicAdd(&o0[col],     acc[mt][nt][0]);
                atomicAdd(&o0[col + 1], acc[mt][nt][1]);
            }
            if (v1) {
                atomicAdd(&o1[col],     acc[mt][nt][2]);
                atomicAdd(&o1[col + 1], acc[mt][nt][3]);
            }
        }
    }
}

// ---------------- stream/event handles ----------------
static cudaStream_t g_s2 = nullptr;
static cudaEvent_t  g_evF = nullptr, g_evJ = nullptr;
static struct _StreamInit {
    _StreamInit() {
        if (cudaStreamCreateWithFlags(&g_s2, cudaStreamNonBlocking) != cudaSuccess) g_s2 = nullptr;
        if (cudaEventCreateWithFlags(&g_evF, cudaEventDisableTiming) != cudaSuccess) g_evF = nullptr;
        if (cudaEventCreateWithFlags(&g_evJ, cudaEventDisableTiming) != cudaSuccess) g_evJ = nullptr;
    }
} g_stream_init;

// ---------------- launch ----------------
extern "C" void kernel_launch(void* const* d_in, const int* in_sizes, int n_in,
                              void* d_out, int out_size) {
    const float* x    = (const float*)d_in[0];
    const int*   idxw = (const int*)d_in[1];
    const float* wts  = (const float*)d_in[2];
    const float* gate = (const float*)d_in[3];
    const float* up   = (const float*)d_in[4];
    const float* down = (const float*)d_in[5];
    float* out = (float*)d_out;

    cudaFuncSetAttribute(gemm_gu_mma,   cudaFuncAttributeMaxDynamicSharedMemorySize, GU_SMEM);
    cudaFuncSetAttribute(gemm_down_mma, cudaFuncAttributeMaxDynamicSharedMemorySize, DN_SMEM);

    __nv_bfloat16 *xh, *xl, *gh, *gl, *uh, *ul, *dh, *dl;
    cudaGetSymbolAddress((void**)&xh, g_xh);
    cudaGetSymbolAddress((void**)&xl, g_xl);
    cudaGetSymbolAddress((void**)&gh, g_gh);
    cudaGetSymbolAddress((void**)&gl, g_gl);
    cudaGetSymbolAddress((void**)&uh, g_uh);
    cudaGetSymbolAddress((void**)&ul, g_ul);
    cudaGetSymbolAddress((void**)&dh, g_dh);
    cudaGetSymbolAddress((void**)&dl, g_dl);

    const int nw = NEXP * INTER_ * HID / 4;
    const int n4 = out_size / 4;
    const bool use_streams = (g_s2 && g_evF && g_evJ);

    if (use_streams) {
        // side stream: zero(out) then split_down, both overlapped with gu path
        cudaEventRecord(g_evF, 0);
        cudaStreamWaitEvent(g_s2, g_evF, 0);
        zero_kernel<<<(n4 + 255) / 256, 256, 0, g_s2>>>((float4*)out, n4);
        split_down_k<<<(nw + 255) / 256, 256, 0, g_s2>>>(
            (const float4*)down, (uint2*)dh, (uint2*)dl, nw);
        cudaEventRecord(g_evJ, g_s2);
    } else {
        zero_kernel<<<(n4 + 255) / 256, 256>>>((float4*)out, n4);
        split_down_k<<<(nw + 255) / 256, 256>>>(
            (const float4*)down, (uint2*)dh, (uint2*)dl, nw);
    }

    route_kernel<<<1, 256>>>(idxw, wts);
    {
        int total = 2 * nw + NTOK * HID / 4;
        split_xgu<<<(total + 255) / 256, 256>>>(
            (const float4*)x, (const float4*)gate, (const float4*)up,
            (uint2*)xh, (uint2*)xl, (uint2*)gh, (uint2*)gl, (uint2*)uh, (uint2*)ul);
    }
    {
        dim3 grid(INTER_ / 128, NSLOT / 128, NEXP);
        gemm_gu_mma<<<grid, 512, GU_SMEM>>>();
    }
    if (use_streams) {
        cudaStreamWaitEvent(0, g_evJ, 0);
    }
    {
        dim3 grid(HID / 128, NSLOT / 128, NEXP);
        gemm_down_mma<<<grid, 256, DN_SMEM>>>(out);
    }
}